// round 2
// baseline (speedup 1.0000x reference)
#include <cuda_runtime.h>
#include <cuda_bf16.h>
#include <cstdint>

// Problem constants (SheafGluingPoly: B=4, M=50000, D=8, E=1600000, POLY_K=3, LAM=1)
#define B_CONST 4
#define D_CONST 8
#define MAX_MBD 1600000   // B*M*D
#define MAX_E   1600000

// Scratch: ping-pong vertex state in transposed [m][b][d] layout (128B/vertex),
// plus packed (src,dst) pairs.
__device__ float g_bufA[MAX_MBD];
__device__ float g_bufB[MAX_MBD];
__device__ int2  g_pair[MAX_E];

// ---------------------------------------------------------------------------
// pack: pair[e] = (src[e], dst[e])
// ---------------------------------------------------------------------------
__global__ void pack_kernel(const int* __restrict__ src,
                            const int* __restrict__ dst,
                            int2* __restrict__ pair, int E)
{
    int i = blockIdx.x * blockDim.x + threadIdx.x;
    if (i < E) pair[i] = make_int2(src[i], dst[i]);
}

// ---------------------------------------------------------------------------
// init: v(A) = transpose(c0), out = pc[0]*c0, acc(B) = 0
// ---------------------------------------------------------------------------
__global__ void init_kernel(const float* __restrict__ c0,
                            const float* __restrict__ pc,
                            float* __restrict__ out,
                            float* __restrict__ v,
                            float* __restrict__ accz,
                            int M)
{
    int i = blockIdx.x * blockDim.x + threadIdx.x;
    int n = M * 32;
    if (i >= n) return;
    int m = i >> 5;
    int t = i & 31;
    int b = t >> 3;
    int d = t & 7;
    int src_idx = (b * M + m) * 8 + d;   // [b][m][d] layout of c0 / out
    float val = c0[src_idx];
    v[i] = val;
    out[src_idx] = pc[0] * val;
    accz[i] = 0.0f;
}

// ---------------------------------------------------------------------------
// edge kernel: one warp per edge. lane t = b*8 + d.
// Row-major per-lane R rows (two float4 chunks, bit2(d)-preswapped).
//   forward (local): r[b][d] = Rs[d][:]·ps[b][:] − Rd[d][:]·pd[b][:]
//   transpose via 3-stage shfl reduce-scatter within each 8-lane b-group:
//     cs[d] = Σ_a Rs[a][d]·r[a],  cd[d] = Σ_a Rd[a][d]·(−r[a])
//   acc[src][b][d] += cs[d];  acc[dst][b][d] += cd[d]
// ---------------------------------------------------------------------------
__global__ void __launch_bounds__(256)
edge_kernel(const float* __restrict__ v,
            const int2*  __restrict__ pair,
            const float* __restrict__ Rsrc,
            const float* __restrict__ Rdst,
            float*       __restrict__ acc,
            int E)
{
    int e = (blockIdx.x * blockDim.x + threadIdx.x) >> 5;
    if (e >= E) return;
    int t = threadIdx.x & 31;
    int d = t & 7;
    int b = t >> 3;
    int swap = (d & 4) << 2;          // 0 or 16 bytes: bit2(d) chunk pre-swap

    int2 pr = __ldg(pair + e);

    const char* RsE = (const char*)Rsrc + (int64_t)e * 256 + d * 32;
    const char* RdE = (const char*)Rdst + (int64_t)e * 256 + d * 32;
    const char* vsB = (const char*)(v + pr.x * 32 + b * 8);
    const char* vdB = (const char*)(v + pr.y * 32 + b * 8);

    // Row d of each matrix, chunk A = the half matching bit2(d), chunk B = other.
    float4 rsA = *(const float4*)(RsE + swap);
    float4 rsB = *(const float4*)(RsE + (swap ^ 16));
    float4 rdA = *(const float4*)(RdE + swap);
    float4 rdB = *(const float4*)(RdE + (swap ^ 16));

    // ps/pd vectors with the SAME chunk pre-swap so FMA pairs align.
    float4 psA = *(const float4*)(vsB + swap);
    float4 psB = *(const float4*)(vsB + (swap ^ 16));
    float4 pdA = *(const float4*)(vdB + swap);
    float4 pdB = *(const float4*)(vdB + (swap ^ 16));

    // forward: r = rowS·ps − rowD·pd   (16 FMA, no shfl)
    float r = rsA.x * psA.x;
    r = fmaf(rsA.y, psA.y, r);
    r = fmaf(rsA.z, psA.z, r);
    r = fmaf(rsA.w, psA.w, r);
    r = fmaf(rsB.x, psB.x, r);
    r = fmaf(rsB.y, psB.y, r);
    r = fmaf(rsB.z, psB.z, r);
    r = fmaf(rsB.w, psB.w, r);
    r = fmaf(rdA.x, -pdA.x, r);
    r = fmaf(rdA.y, -pdA.y, r);
    r = fmaf(rdA.z, -pdA.z, r);
    r = fmaf(rdA.w, -pdA.w, r);
    r = fmaf(rdB.x, -pdB.x, r);
    r = fmaf(rdB.y, -pdB.y, r);
    r = fmaf(rdB.z, -pdB.z, r);
    r = fmaf(rdB.w, -pdB.w, r);

    // transpose products (pre-swapped layout: positions 0..3 = this lane's
    // bit2-half of the logical index space, 4..7 = the other half)
    float nr = -r;
    float cs[8], cd[8];
    cs[0] = rsA.x * r;  cs[1] = rsA.y * r;  cs[2] = rsA.z * r;  cs[3] = rsA.w * r;
    cs[4] = rsB.x * r;  cs[5] = rsB.y * r;  cs[6] = rsB.z * r;  cs[7] = rsB.w * r;
    cd[0] = rdA.x * nr; cd[1] = rdA.y * nr; cd[2] = rdA.z * nr; cd[3] = rdA.w * nr;
    cd[4] = rdB.x * nr; cd[5] = rdB.y * nr; cd[6] = rdB.z * nr; cd[7] = rdB.w * nr;

    const unsigned FULL = 0xffffffffu;

    // stage 4: SEL-free thanks to chunk pre-swap
#pragma unroll
    for (int k = 0; k < 4; k++) {
        cs[k] += __shfl_xor_sync(FULL, cs[k + 4], 4);
        cd[k] += __shfl_xor_sync(FULL, cd[k + 4], 4);
    }

    // stage 2: keep logicals whose bit1 matches bit1(d)
    {
        bool hi = (d & 2);
        float s0 = hi ? cs[0] : cs[2];
        float k0 = hi ? cs[2] : cs[0];
        float s1 = hi ? cs[1] : cs[3];
        float k1 = hi ? cs[3] : cs[1];
        cs[0] = k0 + __shfl_xor_sync(FULL, s0, 2);
        cs[1] = k1 + __shfl_xor_sync(FULL, s1, 2);
        float t0 = hi ? cd[0] : cd[2];
        float u0 = hi ? cd[2] : cd[0];
        float t1 = hi ? cd[1] : cd[3];
        float u1 = hi ? cd[3] : cd[1];
        cd[0] = u0 + __shfl_xor_sync(FULL, t0, 2);
        cd[1] = u1 + __shfl_xor_sync(FULL, t1, 2);
    }

    // stage 1: keep logical whose bit0 matches bit0(d)
    float csF, cdF;
    {
        bool hi = (d & 1);
        float s = hi ? cs[0] : cs[1];
        float k = hi ? cs[1] : cs[0];
        csF = k + __shfl_xor_sync(FULL, s, 1);
        float s2 = hi ? cd[0] : cd[1];
        float k2 = hi ? cd[1] : cd[0];
        cdF = k2 + __shfl_xor_sync(FULL, s2, 1);
    }

    atomicAdd(acc + pr.x * 32 + t, csF);
    atomicAdd(acc + pr.y * 32 + t, cdF);
}

// ---------------------------------------------------------------------------
// update: out[b][m][d] += pc[k] * acc[m][b][d]; optionally zero the other buffer
// ---------------------------------------------------------------------------
__global__ void update_kernel(const float* __restrict__ acc,
                              const float* __restrict__ pc,
                              int k,
                              float* __restrict__ out,
                              float* __restrict__ zother,
                              int M)
{
    int i = blockIdx.x * blockDim.x + threadIdx.x;
    int n = M * 32;
    if (i >= n) return;
    int m = i >> 5;
    int t = i & 31;
    int b = t >> 3;
    int d = t & 7;
    float val = acc[i];
    int oi = (b * M + m) * 8 + d;
    out[oi] += pc[k] * val;
    if (zother) zother[i] = 0.0f;
}

// ---------------------------------------------------------------------------
// launch
// ---------------------------------------------------------------------------
extern "C" void kernel_launch(void* const* d_in, const int* in_sizes, int n_in,
                              void* d_out, int out_size)
{
    const float* c0  = (const float*)d_in[0];
    const int*   src = (const int*)  d_in[1];
    const int*   dst = (const int*)  d_in[2];
    const float* Rs  = (const float*)d_in[3];
    const float* Rd  = (const float*)d_in[4];
    const float* pc  = (const float*)d_in[5];
    float* out = (float*)d_out;

    int E = in_sizes[1];
    int M = in_sizes[0] / (B_CONST * D_CONST);

    float* bufA;  float* bufB;  int2* pairp;
    cudaGetSymbolAddress((void**)&bufA,  g_bufA);
    cudaGetSymbolAddress((void**)&bufB,  g_bufB);
    cudaGetSymbolAddress((void**)&pairp, g_pair);

    int nV = M * 32;
    int tb = 256;
    int gV = (nV + tb - 1) / tb;
    int gE = (E * 32 + tb - 1) / tb;
    int gP = (E + tb - 1) / tb;

    pack_kernel<<<gP, tb>>>(src, dst, pairp, E);
    init_kernel<<<gV, tb>>>(c0, pc, out, bufA, bufB, M);

    // k = 1: B <- L(A); out += pc[1]*B; zero A
    edge_kernel<<<gE, tb>>>(bufA, pairp, Rs, Rd, bufB, E);
    update_kernel<<<gV, tb>>>(bufB, pc, 1, out, bufA, M);

    // k = 2: A <- L(B); out += pc[2]*A; zero B
    edge_kernel<<<gE, tb>>>(bufB, pairp, Rs, Rd, bufA, E);
    update_kernel<<<gV, tb>>>(bufA, pc, 2, out, bufB, M);

    // k = 3: B <- L(A); out += pc[3]*B
    edge_kernel<<<gE, tb>>>(bufA, pairp, Rs, Rd, bufB, E);
    update_kernel<<<gV, tb>>>(bufB, pc, 3, out, nullptr, M);
}

// round 3
// speedup vs baseline: 1.4843x; 1.4843x over previous
#include <cuda_runtime.h>
#include <cuda_bf16.h>
#include <cstdint>

// Problem constants (SheafGluingPoly: B=4, M=50000, D=8, E=1600000, POLY_K=3, LAM=1)
#define B_CONST 4
#define D_CONST 8
#define MAX_MBD 1600000   // B*M*D
#define MAX_E   1600000

// Scratch: ping-pong vertex state in transposed [m][b][d] layout (128B/vertex),
// plus packed (src,dst) pairs.
__device__ float g_bufA[MAX_MBD];
__device__ float g_bufB[MAX_MBD];
__device__ int2  g_pair[MAX_E];

// ---------------------------------------------------------------------------
// init (fused with pair packing):
//   v(A) = transpose(c0), out = pc[0]*c0, acc(B) = 0, pair[e] = (src,dst)
// ---------------------------------------------------------------------------
__global__ void init_kernel(const float* __restrict__ c0,
                            const int*   __restrict__ src,
                            const int*   __restrict__ dst,
                            const float* __restrict__ pc,
                            float* __restrict__ out,
                            float* __restrict__ v,
                            float* __restrict__ accz,
                            int2*  __restrict__ pair,
                            int M, int E)
{
    int i = blockIdx.x * blockDim.x + threadIdx.x;
    int n = M * 32;
    if (i < n) {
        int m = i >> 5;
        int t = i & 31;
        int b = t >> 3;
        int d = t & 7;
        int src_idx = (b * M + m) * 8 + d;   // [b][m][d] layout of c0 / out
        float val = c0[src_idx];
        v[i] = val;
        out[src_idx] = pc[0] * val;
        accz[i] = 0.0f;
    }
    if (i < E) {
        pair[i] = make_int2(src[i], dst[i]);
    }
}

// ---------------------------------------------------------------------------
// edge kernel: one warp per edge. lane t = b*8 + d.
// XOR-permuted column registers: S[k] = Rs[k^d][d], D[k] = Rd[k^d][d].
//   z[k]   = S[k]*ps - D[k]*pd                (partial of r[k^d] over this d)
//   reduce-scatter (keep-low butterfly, no SELs) -> r = r[b][d] at lane (b,d)
//   allgather r_j = shfl_xor(r, j) = r[d^j]; pairs with reg j of S and D:
//     cs[d] = sum_j S[j]*r_j ;  cd[d] = sum_j D[j]*r_j
//   acc[src][b][d] += cs ;  acc[dst][b][d] += -cd
// ---------------------------------------------------------------------------
__global__ void __launch_bounds__(256)
edge_kernel(const float* __restrict__ v,
            const int2*  __restrict__ pair,
            const float* __restrict__ Rsrc,
            const float* __restrict__ Rdst,
            float*       __restrict__ acc,
            int E)
{
    int e = (blockIdx.x * blockDim.x + threadIdx.x) >> 5;
    if (e >= E) return;
    int t = threadIdx.x & 31;
    int d = t & 7;

    int2 pr = __ldg(pair + e);

    // base has bits 5-7 equal to d (d*36 = d*4 | d*32, no carries),
    // so XOR with k*32 selects row (k ^ d): addr = base + (k^d)*32 + d*4.
    uintptr_t baseS = (uintptr_t)Rsrc + (size_t)e * 256 + (unsigned)(d * 36);
    uintptr_t baseD = (uintptr_t)Rdst + (size_t)e * 256 + (unsigned)(d * 36);

    float S[8], D[8];
#pragma unroll
    for (int k = 0; k < 8; k++) {
        S[k] = __ldg((const float*)(baseS ^ (uintptr_t)(k << 5)));
        D[k] = __ldg((const float*)(baseD ^ (uintptr_t)(k << 5)));
    }

    float ps = __ldg(v + pr.x * 32 + t);
    float pd = __ldg(v + pr.y * 32 + t);

    // z[k] = S[k]*ps - D[k]*pd  : partial (this lane's d) of r[b][k^d]
    float z[8];
#pragma unroll
    for (int k = 0; k < 8; k++) {
        z[k] = fmaf(S[k], ps, -(D[k] * pd));
    }

    const unsigned FULL = 0xffffffffu;

    // reduce-scatter: keep-low butterfly, SEL-free thanks to XOR layout.
    // After all stages z[0] = r[b][d] summed over all 8 lanes of the b-group.
#pragma unroll
    for (int k = 0; k < 4; k++) z[k] += __shfl_xor_sync(FULL, z[k + 4], 4);
#pragma unroll
    for (int k = 0; k < 2; k++) z[k] += __shfl_xor_sync(FULL, z[k + 2], 2);
    float r = z[0] + __shfl_xor_sync(FULL, z[1], 1);

    // allgather + transpose FMAs (shuffles shared by cs and cd)
    float cs = S[0] * r;
    float cd = D[0] * r;
#pragma unroll
    for (int j = 1; j < 8; j++) {
        float rj = __shfl_xor_sync(FULL, r, j);   // r[b][d^j]
        cs = fmaf(S[j], rj, cs);
        cd = fmaf(D[j], rj, cd);
    }

    atomicAdd(acc + pr.x * 32 + t, cs);
    atomicAdd(acc + pr.y * 32 + t, -cd);
}

// ---------------------------------------------------------------------------
// update: out[b][m][d] += pc[k] * acc[m][b][d]; optionally zero the other buffer
// ---------------------------------------------------------------------------
__global__ void update_kernel(const float* __restrict__ acc,
                              const float* __restrict__ pc,
                              int k,
                              float* __restrict__ out,
                              float* __restrict__ zother,
                              int M)
{
    int i = blockIdx.x * blockDim.x + threadIdx.x;
    int n = M * 32;
    if (i >= n) return;
    int m = i >> 5;
    int t = i & 31;
    int b = t >> 3;
    int d = t & 7;
    float val = acc[i];
    int oi = (b * M + m) * 8 + d;
    out[oi] += pc[k] * val;
    if (zother) zother[i] = 0.0f;
}

// ---------------------------------------------------------------------------
// launch  (7 launches total; ncu -s 5 captures launch #6 = 3rd edge_kernel)
// ---------------------------------------------------------------------------
extern "C" void kernel_launch(void* const* d_in, const int* in_sizes, int n_in,
                              void* d_out, int out_size)
{
    const float* c0  = (const float*)d_in[0];
    const int*   src = (const int*)  d_in[1];
    const int*   dst = (const int*)  d_in[2];
    const float* Rs  = (const float*)d_in[3];
    const float* Rd  = (const float*)d_in[4];
    const float* pc  = (const float*)d_in[5];
    float* out = (float*)d_out;

    int E = in_sizes[1];
    int M = in_sizes[0] / (B_CONST * D_CONST);

    float* bufA;  float* bufB;  int2* pairp;
    cudaGetSymbolAddress((void**)&bufA,  g_bufA);
    cudaGetSymbolAddress((void**)&bufB,  g_bufB);
    cudaGetSymbolAddress((void**)&pairp, g_pair);

    int nV = M * 32;
    int tb = 256;
    int nInit = (nV > E) ? nV : E;
    int gI = (nInit + tb - 1) / tb;
    int gV = (nV + tb - 1) / tb;
    int gE = (E * 32 + tb - 1) / tb;

    init_kernel<<<gI, tb>>>(c0, src, dst, pc, out, bufA, bufB, pairp, M, E);

    // k = 1: B <- L(A); out += pc[1]*B; zero A
    edge_kernel<<<gE, tb>>>(bufA, pairp, Rs, Rd, bufB, E);
    update_kernel<<<gV, tb>>>(bufB, pc, 1, out, bufA, M);

    // k = 2: A <- L(B); out += pc[2]*A; zero B
    edge_kernel<<<gE, tb>>>(bufB, pairp, Rs, Rd, bufA, E);
    update_kernel<<<gV, tb>>>(bufA, pc, 2, out, bufB, M);

    // k = 3: B <- L(A); out += pc[3]*B
    edge_kernel<<<gE, tb>>>(bufA, pairp, Rs, Rd, bufB, E);
    update_kernel<<<gV, tb>>>(bufB, pc, 3, out, nullptr, M);
}